// round 6
// baseline (speedup 1.0000x reference)
#include <cuda_runtime.h>
#include <math.h>
#include <stdint.h>

#define BATCH 4
#define SEQ   4096
#define DMODEL 2048
#define HD    128
#define DV    256
#define MROWS (BATCH*SEQ)

__device__ float g_Q[MROWS * DV];
__device__ float g_K[MROWS * DV];
__device__ float g_V[MROWS * DV];

// ---------------------------------------------------------------------------
// tf32 helpers
// ---------------------------------------------------------------------------
__device__ __forceinline__ void tf32_split(float x, float& hi, float& lo) {
    float h;
    asm("cvt.rna.tf32.f32 %0, %1;" : "=f"(h) : "f"(x));
    hi = h;
    lo = x - h;
}
__device__ __forceinline__ float tf32_round(float x) {
    float h;
    asm("cvt.rna.tf32.f32 %0, %1;" : "=f"(h) : "f"(x));
    return h;
}
__device__ __forceinline__ void split4(float4 v, float4& h, float4& l) {
    tf32_split(v.x, h.x, l.x);
    tf32_split(v.y, h.y, l.y);
    tf32_split(v.z, h.z, l.z);
    tf32_split(v.w, h.w, l.w);
}

__device__ __forceinline__ void mma_m16n8k8(float c[4], const float a[4], const float b[2]) {
    asm volatile(
        "mma.sync.aligned.m16n8k8.row.col.f32.tf32.tf32.f32 "
        "{%0,%1,%2,%3}, {%4,%5,%6,%7}, {%8,%9}, {%0,%1,%2,%3};"
        : "+f"(c[0]), "+f"(c[1]), "+f"(c[2]), "+f"(c[3])
        : "r"(__float_as_uint(a[0])), "r"(__float_as_uint(a[1])),
          "r"(__float_as_uint(a[2])), "r"(__float_as_uint(a[3])),
          "r"(__float_as_uint(b[0])), "r"(__float_as_uint(b[1])));
}
__device__ __forceinline__ void mma3(float c[4], const float ah[4], const float al[4],
                                     const float bh[2], const float bl[2]) {
    mma_m16n8k8(c, ah, bh);
    mma_m16n8k8(c, al, bh);
    mma_m16n8k8(c, ah, bl);
}

// ---------------------------------------------------------------------------
// Kernel 1: projection GEMM. Interleaved hi/lo smem tiles + LDG prefetch.
// C = x @ W (M=16384, N=256, K=2048); CTA 128x128, 8 warps, BK=32.
// ---------------------------------------------------------------------------
#define PA2 72    // interleaved A pitch (floats): 32*2 + 8; 72 % 32 == 8
#define PB2 264   // interleaved B pitch: 128*2 + 8; 264 % 32 == 8
#define PROJ_SMEM_FLOATS (128*PA2 + 32*PB2)
#define PROJ_SMEM_BYTES  (PROJ_SMEM_FLOATS * 4)

__global__ __launch_bounds__(256, 2) void proj_mma_kernel(
    const float* __restrict__ x, const float* __restrict__ WQ,
    const float* __restrict__ WK, const float* __restrict__ WV)
{
    extern __shared__ float ps[];
    float* A2 = ps;                 // 128 x PA2, (hi,lo) interleaved
    float* B2 = ps + 128 * PA2;     // 32 x PB2

    const int tid = threadIdx.x;
    const int w   = tid >> 5, l = tid & 31;
    const int gid = l >> 2,  tig = l & 3;
    const int wr  = w >> 1,  wc  = w & 1;
    const int m0c = blockIdx.x * 128;
    const int n0c = blockIdx.y * 128;
    const float* __restrict__ W = (blockIdx.z == 0) ? WQ : (blockIdx.z == 1) ? WK : WV;
    float* __restrict__ C = (blockIdx.z == 0) ? g_Q : (blockIdx.z == 1) ? g_K : g_V;

    // staging coordinates
    const int arow = tid >> 3;          // 0..31 (plus p*32)
    const int acol = (tid & 7) * 4;     // 0..28
    const int brow = tid >> 5;          // 0..7  (plus p*8)
    const int bcol = (tid & 31) * 4;    // 0..124

    float acc[2][8][4];
#pragma unroll
    for (int mb = 0; mb < 2; mb++)
#pragma unroll
        for (int nb = 0; nb < 8; nb++)
#pragma unroll
            for (int i = 0; i < 4; i++) acc[mb][nb][i] = 0.f;

    // prefetch chunk 0
    float4 a4[4], b4[4];
#pragma unroll
    for (int p = 0; p < 4; p++)
        a4[p] = *(const float4*)&x[(size_t)(m0c + p * 32 + arow) * DMODEL + acol];
#pragma unroll
    for (int p = 0; p < 4; p++)
        b4[p] = *(const float4*)&W[(size_t)(p * 8 + brow) * DV + n0c + bcol];

    for (int k0 = 0; k0 < DMODEL; k0 += 32) {
        __syncthreads();
        // STS with split, interleaved
#pragma unroll
        for (int p = 0; p < 4; p++) {
            float4 h, lo;
            split4(a4[p], h, lo);
            int base = (p * 32 + arow) * PA2 + 2 * acol;
            *(float4*)&A2[base]     = make_float4(h.x, lo.x, h.y, lo.y);
            *(float4*)&A2[base + 4] = make_float4(h.z, lo.z, h.w, lo.w);
        }
#pragma unroll
        for (int p = 0; p < 4; p++) {
            float4 h, lo;
            split4(b4[p], h, lo);
            int base = (p * 8 + brow) * PB2 + 2 * bcol;
            *(float4*)&B2[base]     = make_float4(h.x, lo.x, h.y, lo.y);
            *(float4*)&B2[base + 4] = make_float4(h.z, lo.z, h.w, lo.w);
        }
        __syncthreads();

        // prefetch next chunk (overlaps with MMA below)
        if (k0 + 32 < DMODEL) {
#pragma unroll
            for (int p = 0; p < 4; p++)
                a4[p] = *(const float4*)&x[(size_t)(m0c + p * 32 + arow) * DMODEL + k0 + 32 + acol];
#pragma unroll
            for (int p = 0; p < 4; p++)
                b4[p] = *(const float4*)&W[(size_t)(k0 + 32 + p * 8 + brow) * DV + n0c + bcol];
        }

#pragma unroll
        for (int ks = 0; ks < 4; ks++) {
            float ah[2][4], al[2][4];
#pragma unroll
            for (int mb = 0; mb < 2; mb++) {
                int ab = (wr * 32 + mb * 16 + gid) * PA2 + (ks * 8 + tig) * 2;
                float2 p0 = *(float2*)&A2[ab];
                float2 p1 = *(float2*)&A2[ab + 8 * PA2];
                float2 p2 = *(float2*)&A2[ab + 8];
                float2 p3 = *(float2*)&A2[ab + 8 * PA2 + 8];
                ah[mb][0] = p0.x; al[mb][0] = p0.y;
                ah[mb][1] = p1.x; al[mb][1] = p1.y;
                ah[mb][2] = p2.x; al[mb][2] = p2.y;
                ah[mb][3] = p3.x; al[mb][3] = p3.y;
            }
#pragma unroll
            for (int nb = 0; nb < 8; nb++) {
                int bb = (ks * 8 + tig) * PB2 + (wc * 64 + nb * 8 + gid) * 2;
                float2 q0 = *(float2*)&B2[bb];
                float2 q1 = *(float2*)&B2[bb + 4 * PB2];
                float bh[2] = {q0.x, q1.x};
                float bl[2] = {q0.y, q1.y};
                mma3(acc[0][nb], ah[0], al[0], bh, bl);
                mma3(acc[1][nb], ah[1], al[1], bh, bl);
            }
        }
    }

#pragma unroll
    for (int mb = 0; mb < 2; mb++) {
        int r0 = m0c + wr * 32 + mb * 16 + gid;
#pragma unroll
        for (int nb = 0; nb < 8; nb++) {
            int cc = n0c + wc * 64 + nb * 8 + 2 * tig;
            *(float2*)&C[(size_t)r0 * DV + cc]       = make_float2(acc[mb][nb][0], acc[mb][nb][1]);
            *(float2*)&C[(size_t)(r0 + 8) * DV + cc] = make_float2(acc[mb][nb][2], acc[mb][nb][3]);
        }
    }
}

// ---------------------------------------------------------------------------
// Kernel 2: flash differential attention.
// BM=64, BN=32, 512 threads (16 warps). K,V hi/lo INTERLEAVED in smem
// (one LDS.64 per split element pair). Q unsplit (split on the fly).
// P tf32-rounded; PV = P*Vh + P*Vl.
// ---------------------------------------------------------------------------
#define ABM 64
#define ABN 32
#define ATHR 512
#define QPITCH 132   // Q (unsplit) row pitch; 132 % 32 == 4
#define KVP 520      // interleaved K/V row pitch; 520 % 32 == 8
#define PPITCH 36    // P row pitch; 36 % 32 == 4

// float offsets
#define SQ   0                               // 2 mats x 64 x 132 = 16896
#define SK2  (SQ + 2 * ABM * QPITCH)         // 32 x 520
#define SV2  (SK2 + ABN * KVP)               // 32 x 520
#define SPH  (SV2 + ABN * KVP)               // 2 mats x 64 x 36
#define SMR  (SPH + 2 * ABM * PPITCH)
#define SLR  (SMR + 128)
#define SFR  (SLR + 128)
#define SLAM (SFR + 128)
#define ATOT (SLAM + 4)
#define ATOT_BYTES (ATOT * 4)

__global__ __launch_bounds__(ATHR, 1) void diff_attn_mma(
    const float* __restrict__ lq1, const float* __restrict__ lq2,
    const float* __restrict__ lk1, const float* __restrict__ lk2,
    float* __restrict__ out)
{
    extern __shared__ float sm[];
    const int tid = threadIdx.x;
    const int w   = tid >> 5, l = tid & 31;
    const int gid = l >> 2,  tig = l & 3;
    const int b   = blockIdx.y;
    const int q0  = blockIdx.x * ABM;
    const float scale = 0.08838834764831845f;  // HD^-0.5

    // lambda scalar
    if (tid < 32) {
        float s1 = 0.f, s2 = 0.f;
        for (int i = l; i < HD; i += 32) {
            s1 += lq1[i] * lk1[i];
            s2 += lq2[i] * lk2[i];
        }
#pragma unroll
        for (int o = 16; o; o >>= 1) {
            s1 += __shfl_xor_sync(0xffffffffu, s1, o);
            s2 += __shfl_xor_sync(0xffffffffu, s2, o);
        }
        if (l == 0) {
            double li = 0.8 - 0.6 * exp(-3.6);
            sm[SLAM] = __expf(s1) + __expf(s2) + (float)li;
        }
    }
    if (tid < 128) { sm[SMR + tid] = -INFINITY; sm[SLR + tid] = 0.f; }

    // Q load + scale (unsplit); mats separated
    for (int idx = tid; idx < ABM * 64; idx += ATHR) {
        int r = idx >> 6, f4 = idx & 63;
        float4 v = *(const float4*)&g_Q[(size_t)(b * SEQ + q0 + r) * DV + f4 * 4];
        v.x *= scale; v.y *= scale; v.z *= scale; v.w *= scale;
        int matq = (f4 >= 32);
        int col  = (f4 - matq * 32) * 4;
        *(float4*)&sm[SQ + matq * (ABM * QPITCH) + r * QPITCH + col] = v;
    }

    // warp roles
    const int mat = w >> 3;
    const int wl  = w & 7;
    const int qk_m = wl >> 1;       // 0..3  (m16 block)
    const int qk_n = wl & 1;        // 0..1  (n16 block)
    const int pv_m = wl >> 2;       // 0..1  (m32 half)
    const int pv_c = wl & 3;        // 0..3  (64-col quadrant)

    const int matQ = SQ + mat * (ABM * QPITCH);
    const int matP = SPH + mat * (ABM * PPITCH);
    const int kcol2 = mat * 256;    // word offset of this mat's K cols (interleaved)

    float O[2][8][4];
#pragma unroll
    for (int mt = 0; mt < 2; mt++)
#pragma unroll
        for (int nt = 0; nt < 8; nt++)
#pragma unroll
            for (int i = 0; i < 4; i++) O[mt][nt][i] = 0.f;

    for (int j0 = 0; j0 < SEQ; j0 += ABN) {
        __syncthreads();  // previous PV done reading K/V
        // stage K and V, split + interleave (hi,lo adjacent)
        for (int idx = tid; idx < ABN * 64; idx += ATHR) {
            int r = idx >> 6, f4 = idx & 63;
            size_t g = (size_t)(b * SEQ + j0 + r) * DV + f4 * 4;
            float4 kv = *(const float4*)&g_K[g];
            float4 vv = *(const float4*)&g_V[g];
            float4 h, lo;
            split4(kv, h, lo);
            int base = r * KVP + 8 * f4;
            *(float4*)&sm[SK2 + base]     = make_float4(h.x, lo.x, h.y, lo.y);
            *(float4*)&sm[SK2 + base + 4] = make_float4(h.z, lo.z, h.w, lo.w);
            split4(vv, h, lo);
            *(float4*)&sm[SV2 + base]     = make_float4(h.x, lo.x, h.y, lo.y);
            *(float4*)&sm[SV2 + base + 4] = make_float4(h.z, lo.z, h.w, lo.w);
        }
        __syncthreads();

        // QK^T: warp computes m16 x n16 of its matrix, k=128
        {
            float c[2][4] = {{0.f,0.f,0.f,0.f},{0.f,0.f,0.f,0.f}};
            const int qbase = matQ + (qk_m * 16 + gid) * QPITCH;
#pragma unroll
            for (int ks = 0; ks < 16; ks++) {
                int ab = qbase + ks * 8 + tig;
                float ah[4], al[4];
                tf32_split(sm[ab],                  ah[0], al[0]);
                tf32_split(sm[ab + 8 * QPITCH],     ah[1], al[1]);
                tf32_split(sm[ab + 4],              ah[2], al[2]);
                tf32_split(sm[ab + 8 * QPITCH + 4], ah[3], al[3]);
#pragma unroll
                for (int nb = 0; nb < 2; nb++) {
                    int bb = SK2 + (qk_n * 16 + nb * 8 + gid) * KVP + kcol2 + (ks * 8 + tig) * 2;
                    float2 q0 = *(float2*)&sm[bb];
                    float2 q1 = *(float2*)&sm[bb + 8];
                    float bh[2] = {q0.x, q1.x};
                    float bl[2] = {q0.y, q1.y};
                    mma3(c[nb], ah, al, bh, bl);
                }
            }
            int rr = qk_m * 16 + gid;
#pragma unroll
            for (int nb = 0; nb < 2; nb++) {
                int cc = qk_n * 16 + nb * 8 + 2 * tig;
                *(float2*)&sm[matP + rr * PPITCH + cc]       = make_float2(c[nb][0], c[nb][1]);
                *(float2*)&sm[matP + (rr + 8) * PPITCH + cc] = make_float2(c[nb][2], c[nb][3]);
            }
        }
        __syncthreads();

        // online softmax: 512 threads = 2 mats x 64 rows x 4 lanes (8 cols each)
        {
            int smat = tid >> 8;
            int srow = (tid >> 2) & 63;
            int sub  = tid & 3;
            int base = SPH + smat * (ABM * PPITCH) + srow * PPITCH + sub * 8;
            float4 v0 = *(float4*)&sm[base];
            float4 v1 = *(float4*)&sm[base + 4];
            float tmax = fmaxf(fmaxf(fmaxf(v0.x, v0.y), fmaxf(v0.z, v0.w)),
                               fmaxf(fmaxf(v1.x, v1.y), fmaxf(v1.z, v1.w)));
            tmax = fmaxf(tmax, __shfl_xor_sync(0xffffffffu, tmax, 1));
            tmax = fmaxf(tmax, __shfl_xor_sync(0xffffffffu, tmax, 2));
            float mold = sm[SMR + smat * 64 + srow];
            float mnew = fmaxf(mold, tmax);
            float e0 = __expf(v0.x - mnew), e1 = __expf(v0.y - mnew);
            float e2 = __expf(v0.z - mnew), e3 = __expf(v0.w - mnew);
            float e4 = __expf(v1.x - mnew), e5 = __expf(v1.y - mnew);
            float e6 = __expf(v1.z - mnew), e7 = __expf(v1.w - mnew);
            *(float4*)&sm[base] =
                make_float4(tf32_round(e0), tf32_round(e1), tf32_round(e2), tf32_round(e3));
            *(float4*)&sm[base + 4] =
                make_float4(tf32_round(e4), tf32_round(e5), tf32_round(e6), tf32_round(e7));
            float sum = (e0 + e1) + (e2 + e3) + (e4 + e5) + (e6 + e7);
            sum += __shfl_xor_sync(0xffffffffu, sum, 1);
            sum += __shfl_xor_sync(0xffffffffu, sum, 2);
            if (sub == 0) {
                float f = __expf(mold - mnew);
                sm[SMR + smat * 64 + srow] = mnew;
                sm[SLR + smat * 64 + srow] = sm[SLR + smat * 64 + srow] * f + sum;
                sm[SFR + smat * 64 + srow] = f;
            }
        }
        __syncthreads();

        // PV: warp = m32 x 64 cols of O{mat}; P tf32 (A), V interleaved (B)
        {
            float f0 = sm[SFR + mat * 64 + pv_m * 32 + gid];
            float f1 = sm[SFR + mat * 64 + pv_m * 32 + gid + 8];
            float f2 = sm[SFR + mat * 64 + pv_m * 32 + 16 + gid];
            float f3 = sm[SFR + mat * 64 + pv_m * 32 + 16 + gid + 8];
#pragma unroll
            for (int nt = 0; nt < 8; nt++) {
                O[0][nt][0] *= f0; O[0][nt][1] *= f0; O[0][nt][2] *= f1; O[0][nt][3] *= f1;
                O[1][nt][0] *= f2; O[1][nt][1] *= f2; O[1][nt][2] *= f3; O[1][nt][3] *= f3;
            }
#pragma unroll
            for (int kk = 0; kk < 4; kk++) {
                float a[2][4];
#pragma unroll
                for (int mt = 0; mt < 2; mt++) {
                    int ab = matP + (pv_m * 32 + mt * 16 + gid) * PPITCH + kk * 8 + tig;
                    a[mt][0] = sm[ab];
                    a[mt][1] = sm[ab + 8 * PPITCH];
                    a[mt][2] = sm[ab + 4];
                    a[mt][3] = sm[ab + 8 * PPITCH + 4];
                }
                int r0w = (kk * 8 + tig) * KVP;
                int r1w = (kk * 8 + tig + 4) * KVP;
#pragma unroll
                for (int nt = 0; nt < 8; nt++) {
                    int col2 = (pv_c * 64 + nt * 8 + gid) * 2;
                    float2 q0 = *(float2*)&sm[SV2 + r0w + col2];
                    float2 q1 = *(float2*)&sm[SV2 + r1w + col2];
                    float bh[2] = {q0.x, q1.x};
                    float bl[2] = {q0.y, q1.y};
                    mma_m16n8k8(O[0][nt], a[0], bh);
                    mma_m16n8k8(O[0][nt], a[0], bl);
                    mma_m16n8k8(O[1][nt], a[1], bh);
                    mma_m16n8k8(O[1][nt], a[1], bl);
                }
            }
        }
    }
    __syncthreads();

    // epilogue: out = O1/l1 - lam*O2/l2; mat1 stages lam*O2/l2 in SQ scratch
    const float lam = sm[SLAM];
    if (mat == 1) {
#pragma unroll
        for (int mt = 0; mt < 2; mt++) {
            int ra = pv_m * 32 + mt * 16 + gid, rb = ra + 8;
            float sa = lam / sm[SLR + 64 + ra];
            float sb = lam / sm[SLR + 64 + rb];
#pragma unroll
            for (int nt = 0; nt < 8; nt++) {
                int cc = pv_c * 64 + nt * 8 + 2 * tig;
                *(float2*)&sm[SQ + ra * 264 + cc] =
                    make_float2(O[mt][nt][0] * sa, O[mt][nt][1] * sa);
                *(float2*)&sm[SQ + rb * 264 + cc] =
                    make_float2(O[mt][nt][2] * sb, O[mt][nt][3] * sb);
            }
        }
    }
    __syncthreads();
    if (mat == 0) {
#pragma unroll
        for (int mt = 0; mt < 2; mt++) {
            int ra = pv_m * 32 + mt * 16 + gid, rb = ra + 8;
            float ia = 1.f / sm[SLR + ra];
            float ib = 1.f / sm[SLR + rb];
            size_t basea = (size_t)(b * SEQ + q0 + ra) * DV;
            size_t baseb = (size_t)(b * SEQ + q0 + rb) * DV;
#pragma unroll
            for (int nt = 0; nt < 8; nt++) {
                int cc = pv_c * 64 + nt * 8 + 2 * tig;
                float2 s2 = *(float2*)&sm[SQ + ra * 264 + cc];
                *(float2*)&out[basea + cc] =
                    make_float2(O[mt][nt][0] * ia - s2.x, O[mt][nt][1] * ia - s2.y);
                s2 = *(float2*)&sm[SQ + rb * 264 + cc];
                *(float2*)&out[baseb + cc] =
                    make_float2(O[mt][nt][2] * ib - s2.x, O[mt][nt][3] * ib - s2.y);
            }
        }
    }
}

// ---------------------------------------------------------------------------
// Launch
// ---------------------------------------------------------------------------
extern "C" void kernel_launch(void* const* d_in, const int* in_sizes, int n_in,
                              void* d_out, int out_size)
{
    const float* x   = (const float*)d_in[0];
    const float* WQ  = (const float*)d_in[1];
    const float* WK  = (const float*)d_in[2];
    const float* WV  = (const float*)d_in[3];
    const float* lq1 = (const float*)d_in[4];
    const float* lq2 = (const float*)d_in[5];
    const float* lk1 = (const float*)d_in[6];
    const float* lk2 = (const float*)d_in[7];
    float* out = (float*)d_out;

    cudaFuncSetAttribute(proj_mma_kernel,
                         cudaFuncAttributeMaxDynamicSharedMemorySize, PROJ_SMEM_BYTES);
    dim3 pgrid(MROWS / 128, DV / 128, 3);
    proj_mma_kernel<<<pgrid, 256, PROJ_SMEM_BYTES>>>(x, WQ, WK, WV);

    cudaFuncSetAttribute(diff_attn_mma,
                         cudaFuncAttributeMaxDynamicSharedMemorySize, ATOT_BYTES);
    dim3 agrid(SEQ / ABM, BATCH);
    diff_attn_mma<<<agrid, ATHR, ATOT_BYTES>>>(lq1, lq2, lk1, lk2, out);
}

// round 7
// speedup vs baseline: 1.3514x; 1.3514x over previous
#include <cuda_runtime.h>
#include <math.h>
#include <stdint.h>

#define BATCH 4
#define SEQ   4096
#define DMODEL 2048
#define HD    128
#define DV    256
#define MROWS (BATCH*SEQ)

__device__ float g_Q[MROWS * DV];
__device__ float g_K[MROWS * DV];
__device__ float g_V[MROWS * DV];

// ---------------------------------------------------------------------------
// helpers
// ---------------------------------------------------------------------------
__device__ __forceinline__ void tf32_split(float x, float& hi, float& lo) {
    float h;
    asm("cvt.rna.tf32.f32 %0, %1;" : "=f"(h) : "f"(x));
    hi = h;
    lo = x - h;
}
__device__ __forceinline__ float tf32_round(float x) {
    float h;
    asm("cvt.rna.tf32.f32 %0, %1;" : "=f"(h) : "f"(x));
    return h;
}
__device__ __forceinline__ void split4(float4 v, float4& h, float4& l) {
    tf32_split(v.x, h.x, l.x);
    tf32_split(v.y, h.y, l.y);
    tf32_split(v.z, h.z, l.z);
    tf32_split(v.w, h.w, l.w);
}

__device__ __forceinline__ void mma_m16n8k8(float c[4], const float a[4], const float b[2]) {
    asm volatile(
        "mma.sync.aligned.m16n8k8.row.col.f32.tf32.tf32.f32 "
        "{%0,%1,%2,%3}, {%4,%5,%6,%7}, {%8,%9}, {%0,%1,%2,%3};"
        : "+f"(c[0]), "+f"(c[1]), "+f"(c[2]), "+f"(c[3])
        : "r"(__float_as_uint(a[0])), "r"(__float_as_uint(a[1])),
          "r"(__float_as_uint(a[2])), "r"(__float_as_uint(a[3])),
          "r"(__float_as_uint(b[0])), "r"(__float_as_uint(b[1])));
}
__device__ __forceinline__ void mma3(float c[4], const float ah[4], const float al[4],
                                     const float bh[2], const float bl[2]) {
    mma_m16n8k8(c, ah, bh);
    mma_m16n8k8(c, al, bh);
    mma_m16n8k8(c, ah, bl);
}

// bf16 pieces (family-common, sm_80+)
__device__ __forceinline__ void mma_bf16(float c[4], const uint32_t a[4], const uint32_t b[2]) {
    asm volatile(
        "mma.sync.aligned.m16n8k16.row.col.f32.bf16.bf16.f32 "
        "{%0,%1,%2,%3}, {%4,%5,%6,%7}, {%8,%9}, {%0,%1,%2,%3};"
        : "+f"(c[0]), "+f"(c[1]), "+f"(c[2]), "+f"(c[3])
        : "r"(a[0]), "r"(a[1]), "r"(a[2]), "r"(a[3]), "r"(b[0]), "r"(b[1]));
}
// pack: e0 -> low 16 bits (even k index), e1 -> high 16 bits
__device__ __forceinline__ uint32_t pack2(float e0, float e1) {
    uint32_t r;
    asm("cvt.rn.bf16x2.f32 %0, %1, %2;" : "=r"(r) : "f"(e1), "f"(e0));
    return r;
}
__device__ __forceinline__ float blo16(uint32_t w) { return __uint_as_float(w << 16); }
__device__ __forceinline__ float bhi16(uint32_t w) { return __uint_as_float(w & 0xffff0000u); }

// ---------------------------------------------------------------------------
// Kernel 1: projection GEMM (exact R5 version: pre-split tf32 smem tiles).
// ---------------------------------------------------------------------------
#define PAP 36
#define PBP 136
#define PROJ_SMEM_FLOATS (128*PAP*2 + 32*PBP*2)
#define PROJ_SMEM_BYTES  (PROJ_SMEM_FLOATS * 4)

__global__ __launch_bounds__(256, 2) void proj_mma_kernel(
    const float* __restrict__ x, const float* __restrict__ WQ,
    const float* __restrict__ WK, const float* __restrict__ WV)
{
    extern __shared__ float ps[];
    float* AH = ps;
    float* AL = AH + 128 * PAP;
    float* BH = AL + 128 * PAP;
    float* BL = BH + 32 * PBP;

    const int tid = threadIdx.x;
    const int w   = tid >> 5, l = tid & 31;
    const int gid = l >> 2,  tig = l & 3;
    const int wr  = w >> 1,  wc  = w & 1;
    const int m0c = blockIdx.x * 128;
    const int n0c = blockIdx.y * 128;
    const float* __restrict__ W = (blockIdx.z == 0) ? WQ : (blockIdx.z == 1) ? WK : WV;
    float* __restrict__ C = (blockIdx.z == 0) ? g_Q : (blockIdx.z == 1) ? g_K : g_V;

    float acc[2][8][4];
#pragma unroll
    for (int mb = 0; mb < 2; mb++)
#pragma unroll
        for (int nb = 0; nb < 8; nb++)
#pragma unroll
            for (int i = 0; i < 4; i++) acc[mb][nb][i] = 0.f;

    for (int k0 = 0; k0 < DMODEL; k0 += 32) {
        __syncthreads();
#pragma unroll
        for (int p = 0; p < 4; p++) {
            int row = p * 32 + (tid >> 3);
            int f4  = (tid & 7) * 4;
            float4 v = *(const float4*)&x[(size_t)(m0c + row) * DMODEL + k0 + f4];
            float4 h, lo;
            split4(v, h, lo);
            *(float4*)&AH[row * PAP + f4] = h;
            *(float4*)&AL[row * PAP + f4] = lo;
        }
#pragma unroll
        for (int p = 0; p < 4; p++) {
            int kr = p * 8 + (tid >> 5);
            int f4 = (tid & 31) * 4;
            float4 v = *(const float4*)&W[(size_t)(k0 + kr) * DV + n0c + f4];
            float4 h, lo;
            split4(v, h, lo);
            *(float4*)&BH[kr * PBP + f4] = h;
            *(float4*)&BL[kr * PBP + f4] = lo;
        }
        __syncthreads();

#pragma unroll
        for (int ks = 0; ks < 4; ks++) {
            float ah[2][4], al[2][4];
#pragma unroll
            for (int mb = 0; mb < 2; mb++) {
                int base = (wr * 32 + mb * 16 + gid) * PAP + ks * 8 + tig;
                ah[mb][0] = AH[base];            al[mb][0] = AL[base];
                ah[mb][1] = AH[base + 8 * PAP];  al[mb][1] = AL[base + 8 * PAP];
                ah[mb][2] = AH[base + 4];        al[mb][2] = AL[base + 4];
                ah[mb][3] = AH[base + 8 * PAP + 4]; al[mb][3] = AL[base + 8 * PAP + 4];
            }
#pragma unroll
            for (int nb = 0; nb < 8; nb++) {
                int bb = (ks * 8 + tig) * PBP + wc * 64 + nb * 8 + gid;
                float bh[2], bl[2];
                bh[0] = BH[bb];            bl[0] = BL[bb];
                bh[1] = BH[bb + 4 * PBP];  bl[1] = BL[bb + 4 * PBP];
                mma3(acc[0][nb], ah[0], al[0], bh, bl);
                mma3(acc[1][nb], ah[1], al[1], bh, bl);
            }
        }
    }

#pragma unroll
    for (int mb = 0; mb < 2; mb++) {
        int r0 = m0c + wr * 32 + mb * 16 + gid;
#pragma unroll
        for (int nb = 0; nb < 8; nb++) {
            int cc = n0c + wc * 64 + nb * 8 + 2 * tig;
            *(float2*)&C[(size_t)r0 * DV + cc]       = make_float2(acc[mb][nb][0], acc[mb][nb][1]);
            *(float2*)&C[(size_t)(r0 + 8) * DV + cc] = make_float2(acc[mb][nb][2], acc[mb][nb][3]);
        }
    }
}

// ---------------------------------------------------------------------------
// Kernel 2: flash differential attention.
// BM=64, BN=32, 512 threads (16 warps).
// QK: bf16 3-term (m16n8k16). Q,K stored as packed bf16x2 hi/lo words.
// PV: as R5 (P tf32-rounded fp32, V tf32 hi/lo fp32, m16n8k8, 2-term).
// ---------------------------------------------------------------------------
#define ABM 64
#define ABN 32
#define ATHR 512
#define QPW 68       // Q packed word pitch (64 words + 4); 68 % 32 == 4
#define KPW 132      // K packed word pitch (128 words + 4); 132 % 32 == 4
#define VPITCH 264   // V fp32 row pitch; 264 % 32 == 8 (tig-indexed rows)
#define PPITCH 36    // P fp32 row pitch; 36 % 32 == 4

// word offsets into shared
#define SQHW 0                              // 2 mats x 64 x 68
#define SQLW (SQHW + 2 * ABM * QPW)         // 8704
#define SKHW (SQLW + 2 * ABM * QPW)         // 17408; 32 x 132
#define SKLW (SKHW + ABN * KPW)             // 21632
#define SVH  (SKLW + ABN * KPW)             // 25856; 32 x 264 fp32
#define SVL  (SVH + ABN * VPITCH)           // 34304
#define SP   (SVL + ABN * VPITCH)           // 42752; 2 mats x 64 x 36 fp32
#define SMR  (SP + 2 * ABM * PPITCH)        // 47360
#define SLR  (SMR + 128)
#define SFR  (SLR + 128)
#define SLAM (SFR + 128)
#define ATOT (SLAM + 4)
#define ATOT_BYTES (ATOT * 4)

__global__ __launch_bounds__(ATHR, 1) void diff_attn_mma(
    const float* __restrict__ lq1, const float* __restrict__ lq2,
    const float* __restrict__ lk1, const float* __restrict__ lk2,
    float* __restrict__ out)
{
    extern __shared__ float sm[];
    uint32_t* smw = (uint32_t*)sm;
    const int tid = threadIdx.x;
    const int w   = tid >> 5, l = tid & 31;
    const int gid = l >> 2,  tig = l & 3;
    const int b   = blockIdx.y;
    const int q0  = blockIdx.x * ABM;
    const float scale = 0.08838834764831845f;  // HD^-0.5

    // lambda scalar
    if (tid < 32) {
        float s1 = 0.f, s2 = 0.f;
        for (int i = l; i < HD; i += 32) {
            s1 += lq1[i] * lk1[i];
            s2 += lq2[i] * lk2[i];
        }
#pragma unroll
        for (int o = 16; o; o >>= 1) {
            s1 += __shfl_xor_sync(0xffffffffu, s1, o);
            s2 += __shfl_xor_sync(0xffffffffu, s2, o);
        }
        if (l == 0) {
            double li = 0.8 - 0.6 * exp(-3.6);
            sm[SLAM] = __expf(s1) + __expf(s2) + (float)li;
        }
    }
    if (tid < 128) { sm[SMR + tid] = -INFINITY; sm[SLR + tid] = 0.f; }

    // Q load + scale, pack to bf16 hi/lo words (once per CTA)
    for (int idx = tid; idx < ABM * 64; idx += ATHR) {
        int r = idx >> 6, f4 = idx & 63;
        float4 v = *(const float4*)&g_Q[(size_t)(b * SEQ + q0 + r) * DV + f4 * 4];
        v.x *= scale; v.y *= scale; v.z *= scale; v.w *= scale;
        uint32_t h0 = pack2(v.x, v.y), h1 = pack2(v.z, v.w);
        float l0 = v.x - blo16(h0), l1 = v.y - bhi16(h0);
        float l2 = v.z - blo16(h1), l3 = v.w - bhi16(h1);
        uint32_t w0 = pack2(l0, l1), w1 = pack2(l2, l3);
        int matq = (f4 >= 32);
        int wcol = (f4 - matq * 32) * 2;
        int qb = matq * (ABM * QPW) + r * QPW + wcol;
        *(uint2*)&smw[SQHW + qb] = make_uint2(h0, h1);
        *(uint2*)&smw[SQLW + qb] = make_uint2(w0, w1);
    }

    // warp roles
    const int mat = w >> 3;
    const int wl  = w & 7;
    const int qk_m = wl >> 1;       // 0..3  (m16 block)
    const int qk_n = wl & 1;        // 0..1  (n16 block)
    const int pv_m = wl >> 2;       // 0..1  (m32 half)
    const int pv_c = wl & 3;        // 0..3  (64-col quadrant)

    const int matQw = mat * (ABM * QPW);
    const int matP  = SP + mat * (ABM * PPITCH);
    const int kwoff = mat * 64;     // word offset of this mat's K features

    float O[2][8][4];
#pragma unroll
    for (int mt = 0; mt < 2; mt++)
#pragma unroll
        for (int nt = 0; nt < 8; nt++)
#pragma unroll
            for (int i = 0; i < 4; i++) O[mt][nt][i] = 0.f;

    for (int j0 = 0; j0 < SEQ; j0 += ABN) {
        __syncthreads();  // previous PV done reading K/V
        // stage K (bf16 hi/lo packed) and V (tf32 fp32 split)
        for (int idx = tid; idx < ABN * 64; idx += ATHR) {
            int r = idx >> 6, f4 = idx & 63;
            size_t g = (size_t)(b * SEQ + j0 + r) * DV + f4 * 4;
            float4 kv = *(const float4*)&g_K[g];
            float4 vv = *(const float4*)&g_V[g];
            uint32_t h0 = pack2(kv.x, kv.y), h1 = pack2(kv.z, kv.w);
            float l0 = kv.x - blo16(h0), l1 = kv.y - bhi16(h0);
            float l2 = kv.z - blo16(h1), l3 = kv.w - bhi16(h1);
            uint32_t w0 = pack2(l0, l1), w1 = pack2(l2, l3);
            int kb = r * KPW + f4 * 2;
            *(uint2*)&smw[SKHW + kb] = make_uint2(h0, h1);
            *(uint2*)&smw[SKLW + kb] = make_uint2(w0, w1);
            float4 h, lo;
            split4(vv, h, lo);
            int vb = r * VPITCH + f4 * 4;
            *(float4*)&sm[SVH + vb] = h;
            *(float4*)&sm[SVL + vb] = lo;
        }
        __syncthreads();

        // QK^T: warp computes m16 x n16 of its matrix, k=128 in 8 bf16 steps
        {
            float c[2][4] = {{0.f,0.f,0.f,0.f},{0.f,0.f,0.f,0.f}};
            const int qrow = matQw + (qk_m * 16 + gid) * QPW;
#pragma unroll
            for (int kk = 0; kk < 8; kk++) {
                int aw = qrow + kk * 8 + tig;
                uint32_t ah[4], al[4];
                ah[0] = smw[SQHW + aw];
                ah[1] = smw[SQHW + aw + 8 * QPW];
                ah[2] = smw[SQHW + aw + 4];
                ah[3] = smw[SQHW + aw + 8 * QPW + 4];
                al[0] = smw[SQLW + aw];
                al[1] = smw[SQLW + aw + 8 * QPW];
                al[2] = smw[SQLW + aw + 4];
                al[3] = smw[SQLW + aw + 8 * QPW + 4];
#pragma unroll
                for (int nb = 0; nb < 2; nb++) {
                    int bw = (qk_n * 16 + nb * 8 + gid) * KPW + kwoff + kk * 8 + tig;
                    uint32_t bh[2], bl[2];
                    bh[0] = smw[SKHW + bw];     bh[1] = smw[SKHW + bw + 4];
                    bl[0] = smw[SKLW + bw];     bl[1] = smw[SKLW + bw + 4];
                    mma_bf16(c[nb], ah, bh);
                    mma_bf16(c[nb], al, bh);
                    mma_bf16(c[nb], ah, bl);
                }
            }
            int rr = qk_m * 16 + gid;
#pragma unroll
            for (int nb = 0; nb < 2; nb++) {
                int cc = qk_n * 16 + nb * 8 + 2 * tig;
                *(float2*)&sm[matP + rr * PPITCH + cc]       = make_float2(c[nb][0], c[nb][1]);
                *(float2*)&sm[matP + (rr + 8) * PPITCH + cc] = make_float2(c[nb][2], c[nb][3]);
            }
        }
        __syncthreads();

        // online softmax: 512 threads = 2 mats x 64 rows x 4 lanes (8 cols each)
        {
            int smat = tid >> 8;
            int srow = (tid >> 2) & 63;
            int sub  = tid & 3;
            int base = SP + smat * (ABM * PPITCH) + srow * PPITCH + sub * 8;
            float4 v0 = *(float4*)&sm[base];
            float4 v1 = *(float4*)&sm[base + 4];
            float tmax = fmaxf(fmaxf(fmaxf(v0.x, v0.y), fmaxf(v0.z, v0.w)),
                               fmaxf(fmaxf(v1.x, v1.y), fmaxf(v1.z, v1.w)));
            tmax = fmaxf(tmax, __shfl_xor_sync(0xffffffffu, tmax, 1));
            tmax = fmaxf(tmax, __shfl_xor_sync(0xffffffffu, tmax, 2));
            float mold = sm[SMR + smat * 64 + srow];
            float mnew = fmaxf(mold, tmax);
            float e0 = __expf(v0.x - mnew), e1 = __expf(v0.y - mnew);
            float e2 = __expf(v0.z - mnew), e3 = __expf(v0.w - mnew);
            float e4 = __expf(v1.x - mnew), e5 = __expf(v1.y - mnew);
            float e6 = __expf(v1.z - mnew), e7 = __expf(v1.w - mnew);
            *(float4*)&sm[base] =
                make_float4(tf32_round(e0), tf32_round(e1), tf32_round(e2), tf32_round(e3));
            *(float4*)&sm[base + 4] =
                make_float4(tf32_round(e4), tf32_round(e5), tf32_round(e6), tf32_round(e7));
            float sum = (e0 + e1) + (e2 + e3) + (e4 + e5) + (e6 + e7);
            sum += __shfl_xor_sync(0xffffffffu, sum, 1);
            sum += __shfl_xor_sync(0xffffffffu, sum, 2);
            if (sub == 0) {
                float f = __expf(mold - mnew);
                sm[SMR + smat * 64 + srow] = mnew;
                sm[SLR + smat * 64 + srow] = sm[SLR + smat * 64 + srow] * f + sum;
                sm[SFR + smat * 64 + srow] = f;
            }
        }
        __syncthreads();

        // PV: warp = m32 x 64 cols of O{mat}; P tf32 (A), V split (B), k8 mma
        {
            float f0 = sm[SFR + mat * 64 + pv_m * 32 + gid];
            float f1 = sm[SFR + mat * 64 + pv_m * 32 + gid + 8];
            float f2 = sm[SFR + mat * 64 + pv_m * 32 + 16 + gid];
            float f3 = sm[SFR + mat * 64 + pv_m * 32 + 16 + gid + 8];
#pragma unroll
            for (int nt = 0; nt < 8; nt++) {
                O[0][nt][0] *= f0; O[0][nt][1] *= f0; O[0][nt][2] *= f1; O[0][nt][3] *= f1;
                O[1][nt][0] *= f2; O[1][nt][1] *= f2; O[1][nt][2] *= f3; O[1][nt][3] *= f3;
            }
#pragma unroll
            for (int kk = 0; kk < 4; kk++) {
                float a[2][4];
#pragma unroll
                for (int mt = 0; mt < 2; mt++) {
                    int ab = matP + (pv_m * 32 + mt * 16 + gid) * PPITCH + kk * 8 + tig;
                    a[mt][0] = sm[ab];
                    a[mt][1] = sm[ab + 8 * PPITCH];
                    a[mt][2] = sm[ab + 4];
                    a[mt][3] = sm[ab + 8 * PPITCH + 4];
                }
#pragma unroll
                for (int nt = 0; nt < 8; nt++) {
                    int col = pv_c * 64 + nt * 8 + gid;
                    int b0 = (kk * 8 + tig) * VPITCH + col;
                    int b1 = (kk * 8 + tig + 4) * VPITCH + col;
                    float bh[2], bl[2];
                    bh[0] = sm[SVH + b0]; bl[0] = sm[SVL + b0];
                    bh[1] = sm[SVH + b1]; bl[1] = sm[SVL + b1];
                    mma_m16n8k8(O[0][nt], a[0], bh);
                    mma_m16n8k8(O[0][nt], a[0], bl);
                    mma_m16n8k8(O[1][nt], a[1], bh);
                    mma_m16n8k8(O[1][nt], a[1], bl);
                }
            }
        }
    }
    __syncthreads();

    // epilogue: out = O1/l1 - lam*O2/l2; mat1 stages lam*O2/l2 in scratch
    // (reuse dead Q region at word 0; pitch 264 rows x 64 fits in 17408 words)
    const float lam = sm[SLAM];
    if (mat == 1) {
#pragma unroll
        for (int mt = 0; mt < 2; mt++) {
            int ra = pv_m * 32 + mt * 16 + gid, rb = ra + 8;
            float sa = lam / sm[SLR + 64 + ra];
            float sb = lam / sm[SLR + 64 + rb];
#pragma unroll
            for (int nt = 0; nt < 8; nt++) {
                int cc = pv_c * 64 + nt * 8 + 2 * tig;
                *(float2*)&sm[ra * 264 + cc] =
                    make_float2(O[mt][nt][0] * sa, O[mt][nt][1] * sa);
                *(float2*)&sm[rb * 264 + cc] =
                    make_float2(O[mt][nt][2] * sb, O[mt][nt][3] * sb);
            }
        }
    }
    __syncthreads();
    if (mat == 0) {
#pragma unroll
        for (int mt = 0; mt < 2; mt++) {
            int ra = pv_m * 32 + mt * 16 + gid, rb = ra + 8;
            float ia = 1.f / sm[SLR + ra];
            float ib = 1.f / sm[SLR + rb];
            size_t basea = (size_t)(b * SEQ + q0 + ra) * DV;
            size_t baseb = (size_t)(b * SEQ + q0 + rb) * DV;
#pragma unroll
            for (int nt = 0; nt < 8; nt++) {
                int cc = pv_c * 64 + nt * 8 + 2 * tig;
                float2 s2 = *(float2*)&sm[ra * 264 + cc];
                *(float2*)&out[basea + cc] =
                    make_float2(O[mt][nt][0] * ia - s2.x, O[mt][nt][1] * ia - s2.y);
                s2 = *(float2*)&sm[rb * 264 + cc];
                *(float2*)&out[baseb + cc] =
                    make_float2(O[mt][nt][2] * ib - s2.x, O[mt][nt][3] * ib - s2.y);
            }
        }
    }
}

// ---------------------------------------------------------------------------
// Launch
// ---------------------------------------------------------------------------
extern "C" void kernel_launch(void* const* d_in, const int* in_sizes, int n_in,
                              void* d_out, int out_size)
{
    const float* x   = (const float*)d_in[0];
    const float* WQ  = (const float*)d_in[1];
    const float* WK  = (const float*)d_in[2];
    const float* WV  = (const float*)d_in[3];
    const float* lq1 = (const float*)d_in[4];
    const float* lq2 = (const float*)d_in[5];
    const float* lk1 = (const float*)d_in[6];
    const float* lk2 = (const float*)d_in[7];
    float* out = (float*)d_out;

    cudaFuncSetAttribute(proj_mma_kernel,
                         cudaFuncAttributeMaxDynamicSharedMemorySize, PROJ_SMEM_BYTES);
    dim3 pgrid(MROWS / 128, DV / 128, 3);
    proj_mma_kernel<<<pgrid, 256, PROJ_SMEM_BYTES>>>(x, WQ, WK, WV);

    cudaFuncSetAttribute(diff_attn_mma,
                         cudaFuncAttributeMaxDynamicSharedMemorySize, ATOT_BYTES);
    dim3 agrid(SEQ / ABM, BATCH);
    diff_attn_mma<<<agrid, ATHR, ATOT_BYTES>>>(lq1, lq2, lk1, lk2, out);
}

// round 8
// speedup vs baseline: 1.7957x; 1.3288x over previous
#include <cuda_runtime.h>
#include <math.h>
#include <stdint.h>

#define BATCH 4
#define SEQ   4096
#define DMODEL 2048
#define HD    128
#define DV    256
#define MROWS (BATCH*SEQ)

__device__ float g_Q[MROWS * DV];
__device__ float g_K[MROWS * DV];
__device__ float g_V[MROWS * DV];

// ---------------------------------------------------------------------------
// helpers
// ---------------------------------------------------------------------------
__device__ __forceinline__ void mma_bf16(float c[4], const uint32_t a[4], const uint32_t b[2]) {
    asm volatile(
        "mma.sync.aligned.m16n8k16.row.col.f32.bf16.bf16.f32 "
        "{%0,%1,%2,%3}, {%4,%5,%6,%7}, {%8,%9}, {%0,%1,%2,%3};"
        : "+f"(c[0]), "+f"(c[1]), "+f"(c[2]), "+f"(c[3])
        : "r"(a[0]), "r"(a[1]), "r"(a[2]), "r"(a[3]), "r"(b[0]), "r"(b[1]));
}
// pack: e0 -> low 16 bits (even k index), e1 -> high 16 bits
__device__ __forceinline__ uint32_t pack2(float e0, float e1) {
    uint32_t r;
    asm("cvt.rn.bf16x2.f32 %0, %1, %2;" : "=r"(r) : "f"(e1), "f"(e0));
    return r;
}
__device__ __forceinline__ float blo16(uint32_t w) { return __uint_as_float(w << 16); }
__device__ __forceinline__ float bhi16(uint32_t w) { return __uint_as_float(w & 0xffff0000u); }

// split float pair (same k-pair) into hi word + lo word
__device__ __forceinline__ void packsplit(float e0, float e1, uint32_t& h, uint32_t& lo) {
    h = pack2(e0, e1);
    lo = pack2(e0 - blo16(h), e1 - bhi16(h));
}

// ---------------------------------------------------------------------------
// Kernel 1: projection GEMM, bf16 3-term. C = x @ W  (16384x256x2048).
// CTA 128x128, 8 warps (warp tile 32x64), BK=32.
// A packed along k (row-major pairs); B packed along k (cross-row pairs).
// ---------------------------------------------------------------------------
#define PAW 20    // A word pitch (rows gid-indexed: 20 % 32 == 4 -> per-phase ok)
#define PBW 136   // B word pitch (rows tig-indexed: 136 % 32 == 8)
#define PROJ_W (128*PAW*2 + 16*PBW*2)
#define PROJ_SMEM_BYTES (PROJ_W * 4)

__global__ __launch_bounds__(256, 2) void proj_mma_kernel(
    const float* __restrict__ x, const float* __restrict__ WQ,
    const float* __restrict__ WK, const float* __restrict__ WV)
{
    extern __shared__ uint32_t pw[];
    uint32_t* AH = pw;
    uint32_t* AL = AH + 128 * PAW;
    uint32_t* BH = AL + 128 * PAW;
    uint32_t* BL = BH + 16 * PBW;

    const int tid = threadIdx.x;
    const int w   = tid >> 5, l = tid & 31;
    const int gid = l >> 2,  tig = l & 3;
    const int wr  = w >> 1,  wc  = w & 1;
    const int m0c = blockIdx.x * 128;
    const int n0c = blockIdx.y * 128;
    const float* __restrict__ W = (blockIdx.z == 0) ? WQ : (blockIdx.z == 1) ? WK : WV;
    float* __restrict__ C = (blockIdx.z == 0) ? g_Q : (blockIdx.z == 1) ? g_K : g_V;

    float acc[2][8][4];
#pragma unroll
    for (int mb = 0; mb < 2; mb++)
#pragma unroll
        for (int nb = 0; nb < 8; nb++)
#pragma unroll
            for (int i = 0; i < 4; i++) acc[mb][nb][i] = 0.f;

    for (int k0 = 0; k0 < DMODEL; k0 += 32) {
        __syncthreads();
        // stage A: 128 rows x 32 features, packed k-pairs within row
#pragma unroll
        for (int p = 0; p < 4; p++) {
            int row = p * 32 + (tid >> 3);
            int fq  = (tid & 7);
            float4 v = *(const float4*)&x[(size_t)(m0c + row) * DMODEL + k0 + fq * 4];
            uint32_t h0, l0, h1, l1;
            packsplit(v.x, v.y, h0, l0);
            packsplit(v.z, v.w, h1, l1);
            int aw = row * PAW + fq * 2;
            *(uint2*)&AH[aw] = make_uint2(h0, h1);
            *(uint2*)&AL[aw] = make_uint2(l0, l1);
        }
        // stage B: pairs along k across adjacent W rows
#pragma unroll
        for (int it = 0; it < 2; it++) {
            int idx = it * 256 + tid;
            int kp = idx >> 5, nq = idx & 31;
            const float* wp = &W[(size_t)(k0 + 2 * kp) * DV + n0c + nq * 4];
            float4 v0 = *(const float4*)wp;
            float4 v1 = *(const float4*)(wp + DV);
            uint32_t h0, l0, h1, l1, h2, l2, h3, l3;
            packsplit(v0.x, v1.x, h0, l0);
            packsplit(v0.y, v1.y, h1, l1);
            packsplit(v0.z, v1.z, h2, l2);
            packsplit(v0.w, v1.w, h3, l3);
            int bw = kp * PBW + nq * 4;
            *(uint4*)&BH[bw] = make_uint4(h0, h1, h2, h3);
            *(uint4*)&BL[bw] = make_uint4(l0, l1, l2, l3);
        }
        __syncthreads();

#pragma unroll
        for (int kk = 0; kk < 2; kk++) {
            uint32_t ah[2][4], al[2][4];
#pragma unroll
            for (int mb = 0; mb < 2; mb++) {
                int rb = (wr * 32 + mb * 16 + gid) * PAW + kk * 8 + tig;
                ah[mb][0] = AH[rb];
                ah[mb][1] = AH[rb + 8 * PAW];
                ah[mb][2] = AH[rb + 4];
                ah[mb][3] = AH[rb + 8 * PAW + 4];
                al[mb][0] = AL[rb];
                al[mb][1] = AL[rb + 8 * PAW];
                al[mb][2] = AL[rb + 4];
                al[mb][3] = AL[rb + 8 * PAW + 4];
            }
#pragma unroll
            for (int nb = 0; nb < 8; nb++) {
                int b0 = (kk * 8 + tig) * PBW + wc * 64 + nb * 8 + gid;
                int b1 = (kk * 8 + tig + 4) * PBW + wc * 64 + nb * 8 + gid;
                uint32_t bh[2] = {BH[b0], BH[b1]};
                uint32_t bl[2] = {BL[b0], BL[b1]};
                mma_bf16(acc[0][nb], ah[0], bh);
                mma_bf16(acc[0][nb], al[0], bh);
                mma_bf16(acc[0][nb], ah[0], bl);
                mma_bf16(acc[1][nb], ah[1], bh);
                mma_bf16(acc[1][nb], al[1], bh);
                mma_bf16(acc[1][nb], ah[1], bl);
            }
        }
    }

#pragma unroll
    for (int mb = 0; mb < 2; mb++) {
        int r0 = m0c + wr * 32 + mb * 16 + gid;
#pragma unroll
        for (int nb = 0; nb < 8; nb++) {
            int cc = n0c + wc * 64 + nb * 8 + 2 * tig;
            *(float2*)&C[(size_t)r0 * DV + cc]       = make_float2(acc[mb][nb][0], acc[mb][nb][1]);
            *(float2*)&C[(size_t)(r0 + 8) * DV + cc] = make_float2(acc[mb][nb][2], acc[mb][nb][3]);
        }
    }
}

// ---------------------------------------------------------------------------
// Kernel 2: flash differential attention, all bf16 3-term, 2 CTAs/SM.
// ABM=32 rows/CTA, ABN=32 keys/tile, 256 threads (8 warps).
// ---------------------------------------------------------------------------
#define ABM 32
#define ABN 32
#define ATHR 256
#define QPW 68       // Q packed word pitch; 68 % 32 == 4 (gid rows)
#define KPW 132      // K packed word pitch; 132 % 32 == 4 (gid rows)
#define VPW 264      // V packed word pitch; 264 % 32 == 8 (tig rows, kp-major)
#define SPP 36       // P region row pitch (raw fp32 32 cols / packed 16+16 words)

// word offsets into shared
#define SQHW 0                            // 2 mats x 32 x 68
#define SQLW (SQHW + 2 * ABM * QPW)       // 4352
#define SKHW (SQLW + 2 * ABM * QPW)       // 8704; 32 x 132
#define SKLW (SKHW + ABN * KPW)           // 12928
#define SVHW (SKLW + ABN * KPW)           // 17152; 16 kp x 264
#define SVLW (SVHW + 16 * VPW)            // 21376
#define SP   (SVLW + 16 * VPW)            // 25600; 2 mats x 32 x 36
#define SMR  (SP + 2 * ABM * SPP)         // 27904
#define SLR  (SMR + 64)
#define SFR  (SLR + 64)
#define SLAM (SFR + 64)
#define ATOT (SLAM + 4)
#define ATOT_BYTES (ATOT * 4)             // ~112.4 KB -> 2 CTAs/SM

__global__ __launch_bounds__(ATHR, 2) void diff_attn_mma(
    const float* __restrict__ lq1, const float* __restrict__ lq2,
    const float* __restrict__ lk1, const float* __restrict__ lk2,
    float* __restrict__ out)
{
    extern __shared__ float sm[];
    uint32_t* smw = (uint32_t*)sm;
    const int tid = threadIdx.x;
    const int w   = tid >> 5, l = tid & 31;
    const int gid = l >> 2,  tig = l & 3;
    const int b   = blockIdx.y;
    const int q0  = blockIdx.x * ABM;
    const float scale = 0.08838834764831845f;  // HD^-0.5

    // lambda scalar
    if (tid < 32) {
        float s1 = 0.f, s2 = 0.f;
        for (int i = l; i < HD; i += 32) {
            s1 += lq1[i] * lk1[i];
            s2 += lq2[i] * lk2[i];
        }
#pragma unroll
        for (int o = 16; o; o >>= 1) {
            s1 += __shfl_xor_sync(0xffffffffu, s1, o);
            s2 += __shfl_xor_sync(0xffffffffu, s2, o);
        }
        if (l == 0) {
            double li = 0.8 - 0.6 * exp(-3.6);
            sm[SLAM] = __expf(s1) + __expf(s2) + (float)li;
        }
    }
    if (tid < 64) { sm[SMR + tid] = -INFINITY; sm[SLR + tid] = 0.f; }

    // Q load + scale, packed bf16 hi/lo (once per CTA)
    for (int idx = tid; idx < ABM * 64; idx += ATHR) {
        int r = idx >> 6, f4 = idx & 63;
        float4 v = *(const float4*)&g_Q[(size_t)(b * SEQ + q0 + r) * DV + f4 * 4];
        v.x *= scale; v.y *= scale; v.z *= scale; v.w *= scale;
        uint32_t h0, l0, h1, l1;
        packsplit(v.x, v.y, h0, l0);
        packsplit(v.z, v.w, h1, l1);
        int matq = (f4 >= 32);
        int qb = matq * (ABM * QPW) + r * QPW + (f4 - matq * 32) * 2;
        *(uint2*)&smw[SQHW + qb] = make_uint2(h0, h1);
        *(uint2*)&smw[SQLW + qb] = make_uint2(l0, l1);
    }

    // warp roles (8 warps)
    const int mat = w >> 2;         // 0 or 1
    const int wl  = w & 3;
    const int qk_m = wl >> 1;       // 0..1 (m16 block)
    const int qk_n = wl & 1;        // 0..1 (n16 block)
    const int pv_m = wl >> 1;       // 0..1 (m16 block)
    const int pv_c = wl & 1;        // 0..1 (128-col half)

    const int matQw = mat * (ABM * QPW);
    const int matP  = SP + mat * (ABM * SPP);
    const int kwoff = mat * 64;

    float O[16][4];
#pragma unroll
    for (int nt = 0; nt < 16; nt++)
#pragma unroll
        for (int i = 0; i < 4; i++) O[nt][i] = 0.f;

    for (int j0 = 0; j0 < SEQ; j0 += ABN) {
        __syncthreads();  // previous tile fully consumed
        // stage K packed hi/lo (feature pairs within row)
        for (int idx = tid; idx < ABN * 64; idx += ATHR) {
            int r = idx >> 6, f4 = idx & 63;
            const float* kp = &g_K[(size_t)(b * SEQ + j0 + r) * DV + f4 * 4];
            float4 kv = *(const float4*)kp;
            uint32_t h0, l0, h1, l1;
            packsplit(kv.x, kv.y, h0, l0);
            packsplit(kv.z, kv.w, h1, l1);
            int kb = r * KPW + f4 * 2;
            *(uint2*)&smw[SKHW + kb] = make_uint2(h0, h1);
            *(uint2*)&smw[SKLW + kb] = make_uint2(l0, l1);
        }
        // stage V packed hi/lo (key pairs across rows)
        for (int idx = tid; idx < 16 * 64; idx += ATHR) {
            int kp = idx >> 6, f4 = idx & 63;
            const float* vp = &g_V[(size_t)(b * SEQ + j0 + 2 * kp) * DV + f4 * 4];
            float4 v0 = *(const float4*)vp;
            float4 v1 = *(const float4*)(vp + DV);
            uint32_t h0, l0, h1, l1, h2, l2, h3, l3;
            packsplit(v0.x, v1.x, h0, l0);
            packsplit(v0.y, v1.y, h1, l1);
            packsplit(v0.z, v1.z, h2, l2);
            packsplit(v0.w, v1.w, h3, l3);
            int vb = kp * VPW + f4 * 4;
            *(uint4*)&smw[SVHW + vb] = make_uint4(h0, h1, h2, h3);
            *(uint4*)&smw[SVLW + vb] = make_uint4(l0, l1, l2, l3);
        }
        __syncthreads();

        // QK^T: warp computes m16 x n16 raw scores of its matrix (k=128)
        {
            float c[2][4] = {{0.f,0.f,0.f,0.f},{0.f,0.f,0.f,0.f}};
            const int qrow = matQw + (qk_m * 16 + gid) * QPW;
#pragma unroll
            for (int kk = 0; kk < 8; kk++) {
                int aw = qrow + kk * 8 + tig;
                uint32_t ah[4], al[4];
                ah[0] = smw[SQHW + aw];
                ah[1] = smw[SQHW + aw + 8 * QPW];
                ah[2] = smw[SQHW + aw + 4];
                ah[3] = smw[SQHW + aw + 8 * QPW + 4];
                al[0] = smw[SQLW + aw];
                al[1] = smw[SQLW + aw + 8 * QPW];
                al[2] = smw[SQLW + aw + 4];
                al[3] = smw[SQLW + aw + 8 * QPW + 4];
#pragma unroll
                for (int nb = 0; nb < 2; nb++) {
                    int bw = (qk_n * 16 + nb * 8 + gid) * KPW + kwoff + kk * 8 + tig;
                    uint32_t bh[2], bl[2];
                    bh[0] = smw[SKHW + bw];  bh[1] = smw[SKHW + bw + 4];
                    bl[0] = smw[SKLW + bw];  bl[1] = smw[SKLW + bw + 4];
                    mma_bf16(c[nb], ah, bh);
                    mma_bf16(c[nb], al, bh);
                    mma_bf16(c[nb], ah, bl);
                }
            }
            int rr = qk_m * 16 + gid;
#pragma unroll
            for (int nb = 0; nb < 2; nb++) {
                int cc = qk_n * 16 + nb * 8 + 2 * tig;
                *(float2*)&sm[matP + rr * SPP + cc]       = make_float2(c[nb][0], c[nb][1]);
                *(float2*)&sm[matP + (rr + 8) * SPP + cc] = make_float2(c[nb][2], c[nb][3]);
            }
        }
        __syncthreads();

        // online softmax: 256 threads = 2 mats x 32 rows x 4 lanes (8 cols).
        // Reads raw fp32 row, writes packed bf16 hi(16w)+lo(16w) IN PLACE
        // (row's lanes are in one warp: reads precede writes in warp order).
        {
            int smat = tid >> 7;
            int srow = (tid >> 2) & 31;
            int sub  = tid & 3;
            int rowb = SP + smat * (ABM * SPP) + srow * SPP;
            float4 v0 = *(float4*)&sm[rowb + sub * 8];
            float4 v1 = *(float4*)&sm[rowb + sub * 8 + 4];
            float tmax = fmaxf(fmaxf(fmaxf(v0.x, v0.y), fmaxf(v0.z, v0.w)),
                               fmaxf(fmaxf(v1.x, v1.y), fmaxf(v1.z, v1.w)));
            tmax = fmaxf(tmax, __shfl_xor_sync(0xffffffffu, tmax, 1));
            tmax = fmaxf(tmax, __shfl_xor_sync(0xffffffffu, tmax, 2));
            float mold = sm[SMR + smat * 32 + srow];
            float mnew = fmaxf(mold, tmax);
            float e0 = __expf(v0.x - mnew), e1 = __expf(v0.y - mnew);
            float e2 = __expf(v0.z - mnew), e3 = __expf(v0.w - mnew);
            float e4 = __expf(v1.x - mnew), e5 = __expf(v1.y - mnew);
            float e6 = __expf(v1.z - mnew), e7 = __expf(v1.w - mnew);
            uint32_t h0, w0, h1, w1, h2, w2, h3, w3;
            packsplit(e0, e1, h0, w0);
            packsplit(e2, e3, h1, w1);
            packsplit(e4, e5, h2, w2);
            packsplit(e6, e7, h3, w3);
            *(uint4*)&smw[rowb + sub * 4]      = make_uint4(h0, h1, h2, h3);
            *(uint4*)&smw[rowb + 16 + sub * 4] = make_uint4(w0, w1, w2, w3);
            float sum = (e0 + e1) + (e2 + e3) + (e4 + e5) + (e6 + e7);
            sum += __shfl_xor_sync(0xffffffffu, sum, 1);
            sum += __shfl_xor_sync(0xffffffffu, sum, 2);
            if (sub == 0) {
                float f = __expf(mold - mnew);
                sm[SMR + smat * 32 + srow] = mnew;
                sm[SLR + smat * 32 + srow] = sm[SLR + smat * 32 + srow] * f + sum;
                sm[SFR + smat * 32 + srow] = f;
            }
        }
        __syncthreads();

        // PV: warp = m16 x 128 cols of O{mat}; bf16 3-term, k=32 (2 k16 steps)
        {
            float fa = sm[SFR + mat * 32 + pv_m * 16 + gid];
            float fb = sm[SFR + mat * 32 + pv_m * 16 + gid + 8];
#pragma unroll
            for (int nt = 0; nt < 16; nt++) {
                O[nt][0] *= fa; O[nt][1] *= fa; O[nt][2] *= fb; O[nt][3] *= fb;
            }
            const int rowb = matP + (pv_m * 16 + gid) * SPP;
#pragma unroll
            for (int kk = 0; kk < 2; kk++) {
                uint32_t ah[4], al[4];
                int aw = rowb + kk * 8 + tig;
                ah[0] = smw[aw];
                ah[1] = smw[aw + 8 * SPP];
                ah[2] = smw[aw + 4];
                ah[3] = smw[aw + 8 * SPP + 4];
                al[0] = smw[aw + 16];
                al[1] = smw[aw + 8 * SPP + 16];
                al[2] = smw[aw + 20];
                al[3] = smw[aw + 8 * SPP + 20];
                int r0w = (kk * 8 + tig) * VPW;
                int r1w = (kk * 8 + tig + 4) * VPW;
#pragma unroll
                for (int nt = 0; nt < 16; nt++) {
                    int col = pv_c * 128 + nt * 8 + gid;
                    uint32_t bh[2] = {smw[SVHW + r0w + col], smw[SVHW + r1w + col]};
                    uint32_t bl[2] = {smw[SVLW + r0w + col], smw[SVLW + r1w + col]};
                    mma_bf16(O[nt], ah, bh);
                    mma_bf16(O[nt], al, bh);
                    mma_bf16(O[nt], ah, bl);
                }
            }
        }
    }
    __syncthreads();

    // epilogue: out = O1/l1 - lam*O2/l2; mat1 stages lam*O2/l2 in scratch
    // (reuse dead Q region: 32 rows x pitch 264 floats = 8448 <= 8704 words)
    const float lam = sm[SLAM];
    const int ra = pv_m * 16 + gid, rb = ra + 8;
    if (mat == 1) {
        float sa = lam / sm[SLR + 32 + ra];
        float sb = lam / sm[SLR + 32 + rb];
#pragma unroll
        for (int nt = 0; nt < 16; nt++) {
            int cc = pv_c * 128 + nt * 8 + 2 * tig;
            *(float2*)&sm[ra * 264 + cc] = make_float2(O[nt][0] * sa, O[nt][1] * sa);
            *(float2*)&sm[rb * 264 + cc] = make_float2(O[nt][2] * sb, O[nt][3] * sb);
        }
    }
    __syncthreads();
    if (mat == 0) {
        float ia = 1.f / sm[SLR + ra];
        float ib = 1.f / sm[SLR + rb];
        size_t basea = (size_t)(b * SEQ + q0 + ra) * DV;
        size_t baseb = (size_t)(b * SEQ + q0 + rb) * DV;
#pragma unroll
        for (int nt = 0; nt < 16; nt++) {
            int cc = pv_c * 128 + nt * 8 + 2 * tig;
            float2 s2 = *(float2*)&sm[ra * 264 + cc];
            *(float2*)&out[basea + cc] =
                make_float2(O[nt][0] * ia - s2.x, O[nt][1] * ia - s2.y);
            s2 = *(float2*)&sm[rb * 264 + cc];
            *(float2*)&out[baseb + cc] =
                make_float2(O[nt][2] * ib - s2.x, O[nt][3] * ib - s2.y);
        }
    }
}

// ---------------------------------------------------------------------------
// Launch
// ---------------------------------------------------------------------------
extern "C" void kernel_launch(void* const* d_in, const int* in_sizes, int n_in,
                              void* d_out, int out_size)
{
    const float* x   = (const float*)d_in[0];
    const float* WQ  = (const float*)d_in[1];
    const float* WK  = (const float*)d_in[2];
    const float* WV  = (const float*)d_in[3];
    const float* lq1 = (const float*)d_in[4];
    const float* lq2 = (const float*)d_in[5];
    const float* lk1 = (const float*)d_in[6];
    const float* lk2 = (const float*)d_in[7];
    float* out = (float*)d_out;

    cudaFuncSetAttribute(proj_mma_kernel,
                         cudaFuncAttributeMaxDynamicSharedMemorySize, PROJ_SMEM_BYTES);
    dim3 pgrid(MROWS / 128, DV / 128, 3);
    proj_mma_kernel<<<pgrid, 256, PROJ_SMEM_BYTES>>>(x, WQ, WK, WV);

    cudaFuncSetAttribute(diff_attn_mma,
                         cudaFuncAttributeMaxDynamicSharedMemorySize, ATOT_BYTES);
    dim3 agrid(SEQ / ABM, BATCH);
    diff_attn_mma<<<agrid, ATHR, ATOT_BYTES>>>(lq1, lq2, lk1, lk2, out);
}

// round 9
// speedup vs baseline: 1.9914x; 1.1089x over previous
#include <cuda_runtime.h>
#include <math.h>
#include <stdint.h>

#define BATCH 4
#define SEQ   4096
#define DMODEL 2048
#define HD    128
#define DV    256
#define MROWS (BATCH*SEQ)

// packed bf16 hi/lo outputs of the projection (word = 2 adjacent elems)
__device__ uint32_t g_Qh[MROWS * 128], g_Ql[MROWS * 128];   // (row, feat-pair)
__device__ uint32_t g_Kh[MROWS * 128], g_Kl[MROWS * 128];   // (row, feat-pair)
__device__ uint32_t g_Vph[(MROWS / 2) * 256], g_Vpl[(MROWS / 2) * 256]; // (key-pair, feat)

// ---------------------------------------------------------------------------
// helpers
// ---------------------------------------------------------------------------
__device__ __forceinline__ void mma_bf16(float c[4], const uint32_t a[4], const uint32_t b[2]) {
    asm volatile(
        "mma.sync.aligned.m16n8k16.row.col.f32.bf16.bf16.f32 "
        "{%0,%1,%2,%3}, {%4,%5,%6,%7}, {%8,%9}, {%0,%1,%2,%3};"
        : "+f"(c[0]), "+f"(c[1]), "+f"(c[2]), "+f"(c[3])
        : "r"(a[0]), "r"(a[1]), "r"(a[2]), "r"(a[3]), "r"(b[0]), "r"(b[1]));
}
__device__ __forceinline__ uint32_t pack2(float e0, float e1) {
    uint32_t r;
    asm("cvt.rn.bf16x2.f32 %0, %1, %2;" : "=r"(r) : "f"(e1), "f"(e0));
    return r;
}
__device__ __forceinline__ float blo16(uint32_t w) { return __uint_as_float(w << 16); }
__device__ __forceinline__ float bhi16(uint32_t w) { return __uint_as_float(w & 0xffff0000u); }
__device__ __forceinline__ void packsplit(float e0, float e1, uint32_t& h, uint32_t& lo) {
    h = pack2(e0, e1);
    lo = pack2(e0 - blo16(h), e1 - bhi16(h));
}
__device__ __forceinline__ uint32_t cvta_shared(const void* p) {
    uint32_t a;
    asm("{ .reg .u64 t; cvta.to.shared.u64 t, %1; cvt.u32.u64 %0, t; }" : "=r"(a) : "l"(p));
    return a;
}
#define CP_ASYNC16(dst, src) \
    asm volatile("cp.async.cg.shared.global [%0], [%1], 16;" :: "r"(dst), "l"(src))
#define CP_COMMIT() asm volatile("cp.async.commit_group;" ::: "memory")
#define CP_WAIT1()  asm volatile("cp.async.wait_group 1;" ::: "memory")
#define CP_WAIT0()  asm volatile("cp.async.wait_group 0;" ::: "memory")

// ---------------------------------------------------------------------------
// Kernel 1: projection GEMM, bf16 3-term (R8 core), packed epilogue.
// ---------------------------------------------------------------------------
#define PAW 20
#define PBW 136
#define PROJ_W (128*PAW*2 + 16*PBW*2)
#define PROJ_SMEM_BYTES (PROJ_W * 4)

__global__ __launch_bounds__(256, 2) void proj_mma_kernel(
    const float* __restrict__ x, const float* __restrict__ WQ,
    const float* __restrict__ WK, const float* __restrict__ WV)
{
    extern __shared__ uint32_t pw[];
    uint32_t* AH = pw;
    uint32_t* AL = AH + 128 * PAW;
    uint32_t* BH = AL + 128 * PAW;
    uint32_t* BL = BH + 16 * PBW;

    const int tid = threadIdx.x;
    const int w   = tid >> 5, l = tid & 31;
    const int gid = l >> 2,  tig = l & 3;
    const int wr  = w >> 1,  wc  = w & 1;
    const int m0c = blockIdx.x * 128;
    const int n0c = blockIdx.y * 128;
    const float* __restrict__ W = (blockIdx.z == 0) ? WQ : (blockIdx.z == 1) ? WK : WV;

    float acc[2][8][4];
#pragma unroll
    for (int mb = 0; mb < 2; mb++)
#pragma unroll
        for (int nb = 0; nb < 8; nb++)
#pragma unroll
            for (int i = 0; i < 4; i++) acc[mb][nb][i] = 0.f;

    for (int k0 = 0; k0 < DMODEL; k0 += 32) {
        __syncthreads();
#pragma unroll
        for (int p = 0; p < 4; p++) {
            int row = p * 32 + (tid >> 3);
            int fq  = (tid & 7);
            float4 v = *(const float4*)&x[(size_t)(m0c + row) * DMODEL + k0 + fq * 4];
            uint32_t h0, l0, h1, l1;
            packsplit(v.x, v.y, h0, l0);
            packsplit(v.z, v.w, h1, l1);
            int aw = row * PAW + fq * 2;
            *(uint2*)&AH[aw] = make_uint2(h0, h1);
            *(uint2*)&AL[aw] = make_uint2(l0, l1);
        }
#pragma unroll
        for (int it = 0; it < 2; it++) {
            int idx = it * 256 + tid;
            int kp = idx >> 5, nq = idx & 31;
            const float* wp = &W[(size_t)(k0 + 2 * kp) * DV + n0c + nq * 4];
            float4 v0 = *(const float4*)wp;
            float4 v1 = *(const float4*)(wp + DV);
            uint32_t h0, l0, h1, l1, h2, l2, h3, l3;
            packsplit(v0.x, v1.x, h0, l0);
            packsplit(v0.y, v1.y, h1, l1);
            packsplit(v0.z, v1.z, h2, l2);
            packsplit(v0.w, v1.w, h3, l3);
            int bw = kp * PBW + nq * 4;
            *(uint4*)&BH[bw] = make_uint4(h0, h1, h2, h3);
            *(uint4*)&BL[bw] = make_uint4(l0, l1, l2, l3);
        }
        __syncthreads();

#pragma unroll
        for (int kk = 0; kk < 2; kk++) {
            uint32_t ah[2][4], al[2][4];
#pragma unroll
            for (int mb = 0; mb < 2; mb++) {
                int rb = (wr * 32 + mb * 16 + gid) * PAW + kk * 8 + tig;
                ah[mb][0] = AH[rb];
                ah[mb][1] = AH[rb + 8 * PAW];
                ah[mb][2] = AH[rb + 4];
                ah[mb][3] = AH[rb + 8 * PAW + 4];
                al[mb][0] = AL[rb];
                al[mb][1] = AL[rb + 8 * PAW];
                al[mb][2] = AL[rb + 4];
                al[mb][3] = AL[rb + 8 * PAW + 4];
            }
#pragma unroll
            for (int nb = 0; nb < 8; nb++) {
                int b0 = (kk * 8 + tig) * PBW + wc * 64 + nb * 8 + gid;
                int b1 = (kk * 8 + tig + 4) * PBW + wc * 64 + nb * 8 + gid;
                uint32_t bh[2] = {BH[b0], BH[b1]};
                uint32_t bl[2] = {BL[b0], BL[b1]};
                mma_bf16(acc[0][nb], ah[0], bh);
                mma_bf16(acc[0][nb], al[0], bh);
                mma_bf16(acc[0][nb], ah[0], bl);
                mma_bf16(acc[1][nb], ah[1], bh);
                mma_bf16(acc[1][nb], al[1], bh);
                mma_bf16(acc[1][nb], ah[1], bl);
            }
        }
    }

    const float qscale = 0.08838834764831845f;  // HD^-0.5
    if (blockIdx.z < 2) {
        // Q (scaled) or K: pack adjacent feature pairs per row
        uint32_t* Gh = (blockIdx.z == 0) ? g_Qh : g_Kh;
        uint32_t* Gl = (blockIdx.z == 0) ? g_Ql : g_Kl;
        const float s = (blockIdx.z == 0) ? qscale : 1.f;
#pragma unroll
        for (int mb = 0; mb < 2; mb++) {
            int r0 = m0c + wr * 32 + mb * 16 + gid;
#pragma unroll
            for (int nb = 0; nb < 8; nb++) {
                int cw = (n0c >> 1) + wc * 32 + nb * 4 + tig;
                uint32_t h, lo;
                packsplit(acc[mb][nb][0] * s, acc[mb][nb][1] * s, h, lo);
                Gh[(size_t)r0 * 128 + cw] = h;
                Gl[(size_t)r0 * 128 + cw] = lo;
                packsplit(acc[mb][nb][2] * s, acc[mb][nb][3] * s, h, lo);
                Gh[(size_t)(r0 + 8) * 128 + cw] = h;
                Gl[(size_t)(r0 + 8) * 128 + cw] = lo;
            }
        }
    } else {
        // V: pack adjacent SEQ-row pairs (cross-row) via shfl
        const bool writer = ((gid & 1) == 0);
#pragma unroll
        for (int mb = 0; mb < 2; mb++) {
#pragma unroll
            for (int nb = 0; nb < 8; nb++) {
                float p0 = __shfl_down_sync(0xffffffffu, acc[mb][nb][0], 4);
                float p1 = __shfl_down_sync(0xffffffffu, acc[mb][nb][1], 4);
                float p2 = __shfl_down_sync(0xffffffffu, acc[mb][nb][2], 4);
                float p3 = __shfl_down_sync(0xffffffffu, acc[mb][nb][3], 4);
                if (writer) {
                    int kp = (m0c + wr * 32 + mb * 16 + gid) >> 1;
                    int cc = n0c + wc * 64 + nb * 8 + 2 * tig;
                    uint32_t h0, l0, h1, l1;
                    packsplit(acc[mb][nb][0], p0, h0, l0);
                    packsplit(acc[mb][nb][1], p1, h1, l1);
                    *(uint2*)&g_Vph[(size_t)kp * 256 + cc] = make_uint2(h0, h1);
                    *(uint2*)&g_Vpl[(size_t)kp * 256 + cc] = make_uint2(l0, l1);
                    packsplit(acc[mb][nb][2], p2, h0, l0);
                    packsplit(acc[mb][nb][3], p3, h1, l1);
                    *(uint2*)&g_Vph[(size_t)(kp + 4) * 256 + cc] = make_uint2(h0, h1);
                    *(uint2*)&g_Vpl[(size_t)(kp + 4) * 256 + cc] = make_uint2(l0, l1);
                }
            }
        }
    }
}

// ---------------------------------------------------------------------------
// Kernel 2: flash differential attention; cp.async-pipelined staging.
// ABM=32 rows/CTA, ABN=32 keys/tile, 256 threads, 2 CTAs/SM.
// ---------------------------------------------------------------------------
#define ABM 32
#define ABN 32
#define ATHR 256
#define QPW 68
#define KPW 132
#define VPW 264
#define SPP 36

#define SQHW 0
#define SQLW (SQHW + 2 * ABM * QPW)
#define SKHW (SQLW + 2 * ABM * QPW)
#define SKLW (SKHW + ABN * KPW)
#define SVHW (SKLW + ABN * KPW)
#define SVLW (SVHW + 16 * VPW)
#define SP   (SVLW + 16 * VPW)
#define SMR  (SP + 2 * ABM * SPP)
#define SLR  (SMR + 64)
#define SFR  (SLR + 64)
#define SLAM (SFR + 64)
#define ATOT (SLAM + 4)
#define ATOT_BYTES (ATOT * 4)

__global__ __launch_bounds__(ATHR, 2) void diff_attn_mma(
    const float* __restrict__ lq1, const float* __restrict__ lq2,
    const float* __restrict__ lk1, const float* __restrict__ lk2,
    float* __restrict__ out)
{
    extern __shared__ float sm[];
    uint32_t* smw = (uint32_t*)sm;
    const uint32_t smbase = cvta_shared(sm);
    const int tid = threadIdx.x;
    const int w   = tid >> 5, l = tid & 31;
    const int gid = l >> 2,  tig = l & 3;
    const int b   = blockIdx.y;
    const int q0  = blockIdx.x * ABM;

    // issue K(0) then V(0) as the first two cp.async groups
    {
#pragma unroll
        for (int it = 0; it < 8; it++) {
            int idx = it * ATHR + tid;
            int bufsel = idx >> 10;
            int i2 = idx & 1023;
            int r = i2 >> 5, c = (i2 & 31) * 4;
            const uint32_t* src = (bufsel ? g_Kl : g_Kh) + (size_t)(b * SEQ + r) * 128 + c;
            uint32_t dst = smbase + ((bufsel ? SKLW : SKHW) + r * KPW + c) * 4;
            CP_ASYNC16(dst, src);
        }
        CP_COMMIT();
#pragma unroll
        for (int it = 0; it < 8; it++) {
            int idx = it * ATHR + tid;
            int bufsel = idx >> 10;
            int i2 = idx & 1023;
            int kp = i2 >> 6, c = (i2 & 63) * 4;
            const uint32_t* src = (bufsel ? g_Vpl : g_Vph) + (size_t)(b * SEQ / 2 + kp) * 256 + c;
            uint32_t dst = smbase + ((bufsel ? SVLW : SVHW) + kp * VPW + c) * 4;
            CP_ASYNC16(dst, src);
        }
        CP_COMMIT();
    }

    // lambda scalar
    if (tid < 32) {
        float s1 = 0.f, s2 = 0.f;
        for (int i = l; i < HD; i += 32) {
            s1 += lq1[i] * lk1[i];
            s2 += lq2[i] * lk2[i];
        }
#pragma unroll
        for (int o = 16; o; o >>= 1) {
            s1 += __shfl_xor_sync(0xffffffffu, s1, o);
            s2 += __shfl_xor_sync(0xffffffffu, s2, o);
        }
        if (l == 0) {
            double li = 0.8 - 0.6 * exp(-3.6);
            sm[SLAM] = __expf(s1) + __expf(s2) + (float)li;
        }
    }
    if (tid < 64) { sm[SMR + tid] = -INFINITY; sm[SLR + tid] = 0.f; }

    // Q stage: plain packed copy (pre-scaled in proj)
    for (int idx = tid; idx < 2048; idx += ATHR) {
        int bufsel = idx >> 10;
        int i2 = idx & 1023;
        int r = i2 >> 5, c = (i2 & 31) * 4;
        uint4 v = *(const uint4*)((bufsel ? g_Ql : g_Qh) + (size_t)(b * SEQ + q0 + r) * 128 + c);
        int matq = (c >= 64);
        int wcol = c - matq * 64;
        *(uint4*)&smw[(bufsel ? SQLW : SQHW) + matq * (ABM * QPW) + r * QPW + wcol] = v;
    }

    // warp roles (8 warps)
    const int mat = w >> 2;
    const int wl  = w & 3;
    const int qk_m = wl >> 1;
    const int qk_n = wl & 1;
    const int pv_m = wl >> 1;
    const int pv_c = wl & 1;

    const int matQw = mat * (ABM * QPW);
    const int matP  = SP + mat * (ABM * SPP);
    const int kwoff = mat * 64;

    float O[16][4];
#pragma unroll
    for (int nt = 0; nt < 16; nt++)
#pragma unroll
        for (int i = 0; i < 4; i++) O[nt][i] = 0.f;

    for (int j0 = 0; j0 < SEQ; j0 += ABN) {
        CP_WAIT1();        // K(j) arrived (V(j) may still be in flight)
        __syncthreads();   // B1: K visible; prev tile fully retired

        // QK^T: warp computes m16 x n16 raw scores of its matrix (k=128)
        {
            float c[2][4] = {{0.f,0.f,0.f,0.f},{0.f,0.f,0.f,0.f}};
            const int qrow = matQw + (qk_m * 16 + gid) * QPW;
#pragma unroll
            for (int kk = 0; kk < 8; kk++) {
                int aw = qrow + kk * 8 + tig;
                uint32_t ah[4], al[4];
                ah[0] = smw[SQHW + aw];
                ah[1] = smw[SQHW + aw + 8 * QPW];
                ah[2] = smw[SQHW + aw + 4];
                ah[3] = smw[SQHW + aw + 8 * QPW + 4];
                al[0] = smw[SQLW + aw];
                al[1] = smw[SQLW + aw + 8 * QPW];
                al[2] = smw[SQLW + aw + 4];
                al[3] = smw[SQLW + aw + 8 * QPW + 4];
#pragma unroll
                for (int nb = 0; nb < 2; nb++) {
                    int bw = (qk_n * 16 + nb * 8 + gid) * KPW + kwoff + kk * 8 + tig;
                    uint32_t bh[2], bl[2];
                    bh[0] = smw[SKHW + bw];  bh[1] = smw[SKHW + bw + 4];
                    bl[0] = smw[SKLW + bw];  bl[1] = smw[SKLW + bw + 4];
                    mma_bf16(c[nb], ah, bh);
                    mma_bf16(c[nb], al, bh);
                    mma_bf16(c[nb], ah, bl);
                }
            }
            int rr = qk_m * 16 + gid;
#pragma unroll
            for (int nb = 0; nb < 2; nb++) {
                int cc = qk_n * 16 + nb * 8 + 2 * tig;
                *(float2*)&sm[matP + rr * SPP + cc]       = make_float2(c[nb][0], c[nb][1]);
                *(float2*)&sm[matP + (rr + 8) * SPP + cc] = make_float2(c[nb][2], c[nb][3]);
            }
        }
        __syncthreads();   // B2: scores complete; K(j) dead

        // issue K(j+1) into the (now dead) K buffer
        {
            int jj = j0 + ABN;
            if (jj >= SEQ) jj = 0;
#pragma unroll
            for (int it = 0; it < 8; it++) {
                int idx = it * ATHR + tid;
                int bufsel = idx >> 10;
                int i2 = idx & 1023;
                int r = i2 >> 5, c = (i2 & 31) * 4;
                const uint32_t* src = (bufsel ? g_Kl : g_Kh) + (size_t)(b * SEQ + jj + r) * 128 + c;
                uint32_t dst = smbase + ((bufsel ? SKLW : SKHW) + r * KPW + c) * 4;
                CP_ASYNC16(dst, src);
            }
            CP_COMMIT();
        }

        // online softmax (reads raw fp32, writes packed bf16 hi/lo in place)
        {
            int smat = tid >> 7;
            int srow = (tid >> 2) & 31;
            int sub  = tid & 3;
            int rowb = SP + smat * (ABM * SPP) + srow * SPP;
            float4 v0 = *(float4*)&sm[rowb + sub * 8];
            float4 v1 = *(float4*)&sm[rowb + sub * 8 + 4];
            float tmax = fmaxf(fmaxf(fmaxf(v0.x, v0.y), fmaxf(v0.z, v0.w)),
                               fmaxf(fmaxf(v1.x, v1.y), fmaxf(v1.z, v1.w)));
            tmax = fmaxf(tmax, __shfl_xor_sync(0xffffffffu, tmax, 1));
            tmax = fmaxf(tmax, __shfl_xor_sync(0xffffffffu, tmax, 2));
            float mold = sm[SMR + smat * 32 + srow];
            float mnew = fmaxf(mold, tmax);
            float e0 = __expf(v0.x - mnew), e1 = __expf(v0.y - mnew);
            float e2 = __expf(v0.z - mnew), e3 = __expf(v0.w - mnew);
            float e4 = __expf(v1.x - mnew), e5 = __expf(v1.y - mnew);
            float e6 = __expf(v1.z - mnew), e7 = __expf(v1.w - mnew);
            uint32_t h0, w0, h1, w1, h2, w2, h3, w3;
            packsplit(e0, e1, h0, w0);
            packsplit(e2, e3, h1, w1);
            packsplit(e4, e5, h2, w2);
            packsplit(e6, e7, h3, w3);
            *(uint4*)&smw[rowb + sub * 4]      = make_uint4(h0, h1, h2, h3);
            *(uint4*)&smw[rowb + 16 + sub * 4] = make_uint4(w0, w1, w2, w3);
            float sum = (e0 + e1) + (e2 + e3) + (e4 + e5) + (e6 + e7);
            sum += __shfl_xor_sync(0xffffffffu, sum, 1);
            sum += __shfl_xor_sync(0xffffffffu, sum, 2);
            if (sub == 0) {
                float f = __expf(mold - mnew);
                sm[SMR + smat * 32 + srow] = mnew;
                sm[SLR + smat * 32 + srow] = sm[SLR + smat * 32 + srow] * f + sum;
                sm[SFR + smat * 32 + srow] = f;
            }
        }
        CP_WAIT1();        // V(j) arrived (K(j+1) may still be in flight)
        __syncthreads();   // B3: softmax + V visible

        // PV: warp = m16 x 128 cols of O{mat}; bf16 3-term, k=32
        {
            float fa = sm[SFR + mat * 32 + pv_m * 16 + gid];
            float fb = sm[SFR + mat * 32 + pv_m * 16 + gid + 8];
#pragma unroll
            for (int nt = 0; nt < 16; nt++) {
                O[nt][0] *= fa; O[nt][1] *= fa; O[nt][2] *= fb; O[nt][3] *= fb;
            }
            const int rowb = matP + (pv_m * 16 + gid) * SPP;
#pragma unroll
            for (int kk = 0; kk < 2; kk++) {
                uint32_t ah[4], al[4];
                int aw = rowb + kk * 8 + tig;
                ah[0] = smw[aw];
                ah[1] = smw[aw + 8 * SPP];
                ah[2] = smw[aw + 4];
                ah[3] = smw[aw + 8 * SPP + 4];
                al[0] = smw[aw + 16];
                al[1] = smw[aw + 8 * SPP + 16];
                al[2] = smw[aw + 20];
                al[3] = smw[aw + 8 * SPP + 20];
                int r0w = (kk * 8 + tig) * VPW;
                int r1w = (kk * 8 + tig + 4) * VPW;
#pragma unroll
                for (int nt = 0; nt < 16; nt++) {
                    int col = pv_c * 128 + nt * 8 + gid;
                    uint32_t bh[2] = {smw[SVHW + r0w + col], smw[SVHW + r1w + col]};
                    uint32_t bl[2] = {smw[SVLW + r0w + col], smw[SVLW + r1w + col]};
                    mma_bf16(O[nt], ah, bh);
                    mma_bf16(O[nt], al, bh);
                    mma_bf16(O[nt], ah, bl);
                }
            }
        }
        __syncthreads();   // B4: PV done; V(j), P dead

        // issue V(j+1)
        {
            int jj = j0 + ABN;
            if (jj >= SEQ) jj = 0;
#pragma unroll
            for (int it = 0; it < 8; it++) {
                int idx = it * ATHR + tid;
                int bufsel = idx >> 10;
                int i2 = idx & 1023;
                int kp = i2 >> 6, c = (i2 & 63) * 4;
                const uint32_t* src =
                    (bufsel ? g_Vpl : g_Vph) + (size_t)((b * SEQ + jj) / 2 + kp) * 256 + c;
                uint32_t dst = smbase + ((bufsel ? SVLW : SVHW) + kp * VPW + c) * 4;
                CP_ASYNC16(dst, src);
            }
            CP_COMMIT();
        }
    }
    CP_WAIT0();
    __syncthreads();

    // epilogue: out = O1/l1 - lam*O2/l2; mat1 stages lam*O2/l2 in Q scratch
    const float lam = sm[SLAM];
    const int ra = pv_m * 16 + gid, rb = ra + 8;
    if (mat == 1) {
        float sa = lam / sm[SLR + 32 + ra];
        float sb = lam / sm[SLR + 32 + rb];
#pragma unroll
        for (int nt = 0; nt < 16; nt++) {
            int cc = pv_c * 128 + nt * 8 + 2 * tig;
            *(float2*)&sm[ra * 264 + cc] = make_float2(O[nt][0] * sa, O[nt][1] * sa);
            *(float2*)&sm[rb * 264 + cc] = make_float2(O[nt][2] * sb, O[nt][3] * sb);
        }
    }
    __syncthreads();
    if (mat == 0) {
        float ia = 1.f / sm[SLR + ra];
        float ib = 1.f / sm[SLR + rb];
        size_t basea = (size_t)(b * SEQ + q0 + ra) * DV;
        size_t baseb = (size_t)(b * SEQ + q0 + rb) * DV;
#pragma unroll
        for (int nt = 0; nt < 16; nt++) {
            int cc = pv_c * 128 + nt * 8 + 2 * tig;
            float2 s2 = *(float2*)&sm[ra * 264 + cc];
            *(float2*)&out[basea + cc] =
                make_float2(O[nt][0] * ia - s2.x, O[nt][1] * ia - s2.y);
            s2 = *(float2*)&sm[rb * 264 + cc];
            *(float2*)&out[baseb + cc] =
                make_float2(O[nt][2] * ib - s2.x, O[nt][3] * ib - s2.y);
        }
    }
}

// ---------------------------------------------------------------------------
// Launch
// ---------------------------------------------------------------------------
extern "C" void kernel_launch(void* const* d_in, const int* in_sizes, int n_in,
                              void* d_out, int out_size)
{
    const float* x   = (const float*)d_in[0];
    const float* WQ  = (const float*)d_in[1];
    const float* WK  = (const float*)d_in[2];
    const float* WV  = (const float*)d_in[3];
    const float* lq1 = (const float*)d_in[4];
    const float* lq2 = (const float*)d_in[5];
    const float* lk1 = (const float*)d_in[6];
    const float* lk2 = (const float*)d_in[7];
    float* out = (float*)d_out;

    cudaFuncSetAttribute(proj_mma_kernel,
                         cudaFuncAttributeMaxDynamicSharedMemorySize, PROJ_SMEM_BYTES);
    dim3 pgrid(MROWS / 128, DV / 128, 3);
    proj_mma_kernel<<<pgrid, 256, PROJ_SMEM_BYTES>>>(x, WQ, WK, WV);

    cudaFuncSetAttribute(diff_attn_mma,
                         cudaFuncAttributeMaxDynamicSharedMemorySize, ATOT_BYTES);
    dim3 agrid(SEQ / ABM, BATCH);
    diff_attn_mma<<<agrid, ATHR, ATOT_BYTES>>>(lq1, lq2, lk1, lk2, out);
}